// round 4
// baseline (speedup 1.0000x reference)
#include <cuda_runtime.h>
#include <cstdint>

// knnLoss via exact grid-accelerated nearest neighbor.
// loss = sum_{b,t} min_s ||s-t||^2 / 120000.
// Grid G^3 over [-R,R], CSR binning of source AND target points.
// Target search: 3x3x3 box (rings 0..1), then Chebyshev shells k=2.. with
// exact stop bound: remaining rings >= k+1 are at distance >= k*h.

#define OUT_HW   100
#define STRIDE   4
#define NPTS     10000
#define NB       4
#define HW       400
#define PLANE    (HW * HW)
#define NALL     (2 * NB * NPTS)      // 80000 points (src + tgt)
#define G        48
#define G3       (G * G * G)          // 110592
#define NSEG     (8 * G3)             // 884736 = 864 * 1024  (src:4, tgt:4)
#define NSCANBLK (NSEG / 1024)        // 864
#define RANGE    6.6f
#define HCELL    0.275f               // 2*RANGE / G
#define INVH     (48.0f / 13.2f)
#define FINF     3.4e38f

__device__ float4 g_pt[NALL];
__device__ int    g_cid[NALL];
__device__ int    g_rank[NALL];
__device__ int    g_cnt[NSEG];
__device__ int    g_off[NSEG];
__device__ int    g_bsum[NSCANBLK];
__device__ float4 g_sorted[NALL];
__device__ float  g_res[NB * NPTS];

// ---------------------------------------------------------------------------
__global__ void zero_kernel() {
    int i = blockIdx.x * blockDim.x + threadIdx.x;
    if (i < NSEG) g_cnt[i] = 0;
}

// ---------------------------------------------------------------------------
// Downsample + pack + count: one thread per (src|tgt, b, m) point.
// ---------------------------------------------------------------------------
__global__ void count_kernel(const float* __restrict__ tgt,
                             const float* __restrict__ src) {
    int i = blockIdx.x * blockDim.x + threadIdx.x;
    if (i >= NALL) return;
    int which = i / (NB * NPTS);        // 0 = source seg first, 1 = target
    int r = i - which * (NB * NPTS);
    int b = r / NPTS;
    int m = r - b * NPTS;
    int h = (m / OUT_HW) * STRIDE;
    int w = (m - (m / OUT_HW) * OUT_HW) * STRIDE;
    // which==0 -> SOURCE points (segment 0), which==1 -> TARGET points
    const float* p = (which == 0 ? src : tgt) + (size_t)b * 3 * PLANE + h * HW + w;
    float x = p[0];
    float y = p[PLANE];
    float z = p[2 * PLANE];
    float nrm = fmaf(x, x, fmaf(y, y, z * z));

    int cx = (int)floorf((x + RANGE) * INVH);
    int cy = (int)floorf((y + RANGE) * INVH);
    int cz = (int)floorf((z + RANGE) * INVH);
    cx = min(max(cx, 0), G - 1);
    cy = min(max(cy, 0), G - 1);
    cz = min(max(cz, 0), G - 1);
    int cell = (which * NB + b) * G3 + (cz * G + cy) * G + cx;

    g_pt[i] = make_float4(x, y, z, nrm);
    g_cid[i] = cell;
    g_rank[i] = atomicAdd(&g_cnt[cell], 1);
}

// ---------------------------------------------------------------------------
// Scan pass 1: per-block (1024) exclusive scan of counts; block totals out.
// ---------------------------------------------------------------------------
__global__ void __launch_bounds__(1024) scan1_kernel() {
    __shared__ int sdata[1024];
    int tid = threadIdx.x;
    int gid = blockIdx.x * 1024 + tid;
    int v = g_cnt[gid];
    sdata[tid] = v;
    __syncthreads();
    #pragma unroll
    for (int s = 1; s < 1024; s <<= 1) {
        int a = (tid >= s) ? sdata[tid - s] : 0;
        __syncthreads();
        sdata[tid] += a;
        __syncthreads();
    }
    g_off[gid] = sdata[tid] - v;         // exclusive
    if (tid == 1023) g_bsum[blockIdx.x] = sdata[1023];
}

// Scan pass 2: exclusive scan of the 864 block sums (single block).
__global__ void __launch_bounds__(1024) scan2_kernel() {
    __shared__ int sdata[1024];
    int tid = threadIdx.x;
    int v = (tid < NSCANBLK) ? g_bsum[tid] : 0;
    sdata[tid] = v;
    __syncthreads();
    #pragma unroll
    for (int s = 1; s < 1024; s <<= 1) {
        int a = (tid >= s) ? sdata[tid - s] : 0;
        __syncthreads();
        sdata[tid] += a;
        __syncthreads();
    }
    if (tid < NSCANBLK) g_bsum[tid] = sdata[tid] - v;   // exclusive
}

// Scan pass 3: add block bases back.
__global__ void __launch_bounds__(1024) addback_kernel() {
    int gid = blockIdx.x * 1024 + threadIdx.x;
    g_off[gid] += g_bsum[blockIdx.x];
}

// ---------------------------------------------------------------------------
// Scatter points into CSR order.
// ---------------------------------------------------------------------------
__global__ void scatter_kernel() {
    int i = blockIdx.x * blockDim.x + threadIdx.x;
    if (i >= NALL) return;
    int pos = g_off[g_cid[i]] + g_rank[i];
    g_sorted[pos] = g_pt[i];
}

// ---------------------------------------------------------------------------
// Search: one thread per target (in cell-sorted order => warp-coherent).
// Source segment for batch b starts at cells [b*G3, (b+1)*G3).
// ---------------------------------------------------------------------------
__device__ __forceinline__ float scan_cell(int cell, float ax, float ay,
                                           float az, float t2, float best) {
    int st = g_off[cell];
    int n  = g_cnt[cell];
    for (int p = st; p < st + n; p++) {
        float4 s = g_sorted[p];
        float d = fmaf(s.x, ax, fmaf(s.y, ay, fmaf(s.z, az, s.w + t2)));
        best = fminf(best, d);
    }
    return best;
}

__global__ void __launch_bounds__(128) search_kernel() {
    int j = blockIdx.x * blockDim.x + threadIdx.x;
    if (j >= NB * NPTS) return;
    float4 tv = g_sorted[NB * NPTS + j];   // targets occupy second half
    int b = j / NPTS;                      // each batch segment is exactly NPTS

    float ax = -2.0f * tv.x, ay = -2.0f * tv.y, az = -2.0f * tv.z;
    float t2 = tv.w;

    int cx = (int)floorf((tv.x + RANGE) * INVH);
    int cy = (int)floorf((tv.y + RANGE) * INVH);
    int cz = (int)floorf((tv.z + RANGE) * INVH);
    cx = min(max(cx, 0), G - 1);
    cy = min(max(cy, 0), G - 1);
    cz = min(max(cz, 0), G - 1);
    int segbase = b * G3;

    float best = FINF;

    // rings 0..1: 3x3x3 box
    {
        int z0 = max(cz - 1, 0), z1 = min(cz + 1, G - 1);
        int y0 = max(cy - 1, 0), y1 = min(cy + 1, G - 1);
        int x0 = max(cx - 1, 0), x1 = min(cx + 1, G - 1);
        for (int zz = z0; zz <= z1; zz++)
            for (int yy = y0; yy <= y1; yy++) {
                int rowbase = segbase + (zz * G + yy) * G;
                for (int xx = x0; xx <= x1; xx++)
                    best = scan_cell(rowbase + xx, ax, ay, az, t2, best);
            }
    }

    // shells k = 2.. with exact stop bound
    int k = 1;
    while (k < G) {
        float kb = (float)k * HCELL;
        if (best <= kb * kb * 0.9999f) break;
        k++;
        for (int dz = -k; dz <= k; dz++) {
            int zz = cz + dz;
            if (zz < 0 || zz >= G) continue;
            int adz = dz < 0 ? -dz : dz;
            for (int dy = -k; dy <= k; dy++) {
                int yy = cy + dy;
                if (yy < 0 || yy >= G) continue;
                int ady = dy < 0 ? -dy : dy;
                int rowbase = segbase + (zz * G + yy) * G;
                int step = (adz == k || ady == k) ? 1 : 2 * k;
                for (int dx = -k; dx <= k; dx += step) {
                    int xx = cx + dx;
                    if (xx < 0 || xx >= G) continue;
                    best = scan_cell(rowbase + xx, ax, ay, az, t2, best);
                }
            }
        }
    }

    g_res[j] = best;
}

// ---------------------------------------------------------------------------
__global__ void __launch_bounds__(1024) reduce_kernel(float* __restrict__ out) {
    __shared__ float red[1024];
    float sum = 0.0f;
    for (int i = threadIdx.x; i < NB * NPTS; i += 1024)
        sum += g_res[i];
    red[threadIdx.x] = sum;
    __syncthreads();
    #pragma unroll
    for (int s = 512; s > 0; s >>= 1) {
        if (threadIdx.x < s) red[threadIdx.x] += red[threadIdx.x + s];
        __syncthreads();
    }
    if (threadIdx.x == 0)
        out[0] = red[0] * (1.0f / (float)(NB * NPTS * 3));
}

// ---------------------------------------------------------------------------
extern "C" void kernel_launch(void* const* d_in, const int* in_sizes, int n_in,
                              void* d_out, int out_size) {
    const float* tgt = (const float*)d_in[0];   // target_pc (4,3,400,400)
    const float* src = (const float*)d_in[1];   // source_pc (4,3,400,400)
    float* out = (float*)d_out;

    zero_kernel<<<NSCANBLK, 1024>>>();
    count_kernel<<<(NALL + 255) / 256, 256>>>(tgt, src);
    scan1_kernel<<<NSCANBLK, 1024>>>();
    scan2_kernel<<<1, 1024>>>();
    addback_kernel<<<NSCANBLK, 1024>>>();
    scatter_kernel<<<(NALL + 255) / 256, 256>>>();
    search_kernel<<<(NB * NPTS + 127) / 128, 128>>>();
    reduce_kernel<<<1, 1024>>>(out);
}

// round 7
// speedup vs baseline: 3.4878x; 3.4878x over previous
#include <cuda_runtime.h>
#include <cstdint>

// knnLoss via exact grid-pruned NN:  loss = sum_{b,t} min_s ||s-t||^2 / 120000.
// Phase A: 3x3x3 cell box scan (row-merged CSR). Exact stop bound: any source
// outside the box is >= h away, so best <= h^2 is provably the true min.
// Phase B: targets failing the bound (~1%, tails) -> warp-cooperative brute
// scan over all 10000 sources of their batch. No shell walking anywhere.

#define OUT_HW   100
#define STRIDE   4
#define NPTS     10000
#define NB       4
#define HW       400
#define PLANE    (HW * HW)
#define NALL     (2 * NB * NPTS)      // 80000
#define G        16
#define G3       (G * G * G)          // 4096
#define NSEG     (8 * G3)             // 32768 (src segs 0..3, tgt segs 4..7)
#define NSCANBLK (NSEG / 1024)        // 32
#define RANGE    3.2f
#define HCELL    0.4f
#define INVH     2.5f
#define H2       (HCELL * HCELL)      // 0.16
#define FINF     3.4e38f

__device__ float4 g_pt[NALL];
__device__ int    g_cid[NALL];
__device__ int    g_rank[NALL];
__device__ int    g_cnt[NSEG];
__device__ int    g_off[NSEG];
__device__ int    g_bsum[NSCANBLK];
__device__ float4 g_sorted[NALL];
__device__ float  g_res[NB * NPTS];
__device__ int    g_fb[NB * NPTS];
__device__ int    g_nfb;

// ---------------------------------------------------------------------------
__global__ void zero_kernel() {
    int i = blockIdx.x * blockDim.x + threadIdx.x;
    if (i < NSEG) g_cnt[i] = 0;
    if (i == 0) g_nfb = 0;
}

// ---------------------------------------------------------------------------
// Downsample + pack + bin-count. which==0 -> sources (segs 0..3),
// which==1 -> targets (segs 4..7).
// ---------------------------------------------------------------------------
__global__ void count_kernel(const float* __restrict__ tgt,
                             const float* __restrict__ src) {
    int i = blockIdx.x * blockDim.x + threadIdx.x;
    if (i >= NALL) return;
    int which = i / (NB * NPTS);
    int r = i - which * (NB * NPTS);
    int b = r / NPTS;
    int m = r - b * NPTS;
    int h = (m / OUT_HW) * STRIDE;
    int w = (m - (m / OUT_HW) * OUT_HW) * STRIDE;
    const float* p = (which == 0 ? src : tgt) + (size_t)b * 3 * PLANE + h * HW + w;
    float x = p[0];
    float y = p[PLANE];
    float z = p[2 * PLANE];
    float nrm = fmaf(x, x, fmaf(y, y, z * z));

    int cx = min(max((int)floorf((x + RANGE) * INVH), 0), G - 1);
    int cy = min(max((int)floorf((y + RANGE) * INVH), 0), G - 1);
    int cz = min(max((int)floorf((z + RANGE) * INVH), 0), G - 1);
    int cell = (which * NB + b) * G3 + (cz * G + cy) * G + cx;

    g_pt[i] = make_float4(x, y, z, nrm);
    g_cid[i] = cell;
    g_rank[i] = atomicAdd(&g_cnt[cell], 1);
}

// ---------------------------------------------------------------------------
// CSR offsets: 3-pass scan over 32768 counts.
// ---------------------------------------------------------------------------
__global__ void __launch_bounds__(1024) scan1_kernel() {
    __shared__ int sdata[1024];
    int tid = threadIdx.x;
    int gid = blockIdx.x * 1024 + tid;
    int v = g_cnt[gid];
    sdata[tid] = v;
    __syncthreads();
    #pragma unroll
    for (int s = 1; s < 1024; s <<= 1) {
        int a = (tid >= s) ? sdata[tid - s] : 0;
        __syncthreads();
        sdata[tid] += a;
        __syncthreads();
    }
    g_off[gid] = sdata[tid] - v;
    if (tid == 1023) g_bsum[blockIdx.x] = sdata[1023];
}

__global__ void scan2_kernel() {     // 1 block, 32 threads (warp scan)
    int lane = threadIdx.x;
    int v = g_bsum[lane];
    int x = v;
    #pragma unroll
    for (int s = 1; s < 32; s <<= 1) {
        int o = __shfl_up_sync(0xffffffffu, x, s);
        if (lane >= s) x += o;
    }
    g_bsum[lane] = x - v;            // exclusive
}

__global__ void __launch_bounds__(1024) addback_kernel() {
    int gid = blockIdx.x * 1024 + threadIdx.x;
    g_off[gid] += g_bsum[blockIdx.x];
}

// ---------------------------------------------------------------------------
__global__ void scatter_kernel() {
    int i = blockIdx.x * blockDim.x + threadIdx.x;
    if (i >= NALL) return;
    int pos = g_off[g_cid[i]] + g_rank[i];
    g_sorted[pos] = g_pt[i];
}

// ---------------------------------------------------------------------------
// Phase A: 3x3x3 box scan, one thread per target (cell-sorted => coherent).
// Each (z,y) row of <=3 cells is one contiguous CSR segment.
// ---------------------------------------------------------------------------
__global__ void __launch_bounds__(128) searchA_kernel() {
    int j = blockIdx.x * blockDim.x + threadIdx.x;
    if (j >= NB * NPTS) return;
    float4 tv = g_sorted[NB * NPTS + j];   // targets are the second half
    int b = j / NPTS;                      // batch segments are exactly NPTS

    float ax = -2.0f * tv.x, ay = -2.0f * tv.y, az = -2.0f * tv.z;

    int cx = min(max((int)floorf((tv.x + RANGE) * INVH), 0), G - 1);
    int cy = min(max((int)floorf((tv.y + RANGE) * INVH), 0), G - 1);
    int cz = min(max((int)floorf((tv.z + RANGE) * INVH), 0), G - 1);
    int segbase = b * G3;
    int x0 = max(cx - 1, 0), x1 = min(cx + 1, G - 1);

    float best = FINF;
    #pragma unroll
    for (int dz = -1; dz <= 1; dz++) {
        int zz = min(max(cz + dz, 0), G - 1);     // clamp may duplicate: harmless
        #pragma unroll
        for (int dy = -1; dy <= 1; dy++) {
            int yy = min(max(cy + dy, 0), G - 1);
            int row = segbase + (zz * G + yy) * G;
            int st = g_off[row + x0];
            int en = g_off[row + x1] + g_cnt[row + x1];
            for (int p = st; p < en; p++) {
                float4 s = g_sorted[p];
                float d = fmaf(s.x, ax, fmaf(s.y, ay, fmaf(s.z, az, s.w)));
                best = fminf(best, d);
            }
        }
    }
    float full = best + tv.w;                      // + ||t||^2
    g_res[j] = full;
    if (full > 0.9995f * H2) {                     // bound not proven -> phase B
        int slot = atomicAdd(&g_nfb, 1);
        g_fb[slot] = j;
    }
}

// ---------------------------------------------------------------------------
// Phase B: warp-cooperative exact scan over all NPTS sources of the batch.
// ---------------------------------------------------------------------------
__global__ void __launch_bounds__(256) fallback_kernel() {
    int nfb = g_nfb;
    int gw = (blockIdx.x * 256 + threadIdx.x) >> 5;
    int lane = threadIdx.x & 31;
    int nw = gridDim.x * 8;
    for (int e = gw; e < nfb; e += nw) {
        int j = g_fb[e];
        float4 tv = g_sorted[NB * NPTS + j];
        int b = j / NPTS;
        float ax = -2.0f * tv.x, ay = -2.0f * tv.y, az = -2.0f * tv.z;
        const float4* sp = g_sorted + b * NPTS;    // whole batch-b source seg
        float best = FINF;
        for (int p = lane; p < NPTS; p += 32) {
            float4 s = sp[p];
            float d = fmaf(s.x, ax, fmaf(s.y, ay, fmaf(s.z, az, s.w)));
            best = fminf(best, d);
        }
        #pragma unroll
        for (int o = 16; o > 0; o >>= 1)
            best = fminf(best, __shfl_xor_sync(0xffffffffu, best, o));
        if (lane == 0) g_res[j] = best + tv.w;
    }
}

// ---------------------------------------------------------------------------
__global__ void __launch_bounds__(1024) reduce_kernel(float* __restrict__ out) {
    __shared__ float red[1024];
    float sum = 0.0f;
    for (int i = threadIdx.x; i < NB * NPTS; i += 1024)
        sum += g_res[i];
    red[threadIdx.x] = sum;
    __syncthreads();
    #pragma unroll
    for (int s = 512; s > 0; s >>= 1) {
        if (threadIdx.x < s) red[threadIdx.x] += red[threadIdx.x + s];
        __syncthreads();
    }
    if (threadIdx.x == 0)
        out[0] = red[0] * (1.0f / (float)(NB * NPTS * 3));
}

// ---------------------------------------------------------------------------
extern "C" void kernel_launch(void* const* d_in, const int* in_sizes, int n_in,
                              void* d_out, int out_size) {
    const float* tgt = (const float*)d_in[0];   // target_pc (4,3,400,400)
    const float* src = (const float*)d_in[1];   // source_pc (4,3,400,400)
    float* out = (float*)d_out;

    zero_kernel<<<NSCANBLK, 1024>>>();
    count_kernel<<<(NALL + 255) / 256, 256>>>(tgt, src);
    scan1_kernel<<<NSCANBLK, 1024>>>();
    scan2_kernel<<<1, 32>>>();
    addback_kernel<<<NSCANBLK, 1024>>>();
    scatter_kernel<<<(NALL + 255) / 256, 256>>>();
    searchA_kernel<<<(NB * NPTS + 127) / 128, 128>>>();
    fallback_kernel<<<80, 256>>>();
    reduce_kernel<<<1, 1024>>>(out);
}